// round 3
// baseline (speedup 1.0000x reference)
#include <cuda_runtime.h>

// Swap_18957985644706: channel-group roll permutation, ILP=8 + streaming hints.
// x: (B=32, C=256, H=64, W=64) fp32, row-major.
// out group 0 (c in [0,64)):    x[b, c+64, (h-1)%64, w]
// out group 1 (c in [64,128)):  x[b, c-64, (h+1)%64, w]
// out group 2 (c in [128,192)): x[b, c+64, h, (w-1)%64]
// out group 3 (c in [192,256)): x[b, c-64, h, (w+1)%64]
//
// Each thread handles 8 output float4s at indices tid + k*CHUNK (k=0..7).
// CHUNK = 2^20 lands entirely in the batch bits of the linear index, so
// c/h/w4/group and the shuffle lane pattern are shared across all 8 chunks
// and the source addresses differ only by k*CHUNK. Loads are front-batched
// (MLP=8); all traffic uses streaming (evict-first) cache hints since there
// is zero reuse and the tensor exceeds L2.

static constexpr unsigned TOTAL_F4 = 32u * 256u * 64u * 16u;   // 8,388,608 = 2^23
static constexpr unsigned CHUNK    = TOTAL_F4 / 8u;            // 1,048,576 = 2^20
static constexpr unsigned THREADS  = 256u;
static constexpr int      ILP      = 8;

__global__ void __launch_bounds__(THREADS) swap_roll_kernel(
    const float4* __restrict__ in, float4* __restrict__ out)
{
    unsigned tid = blockIdx.x * THREADS + threadIdx.x;

    unsigned w4 = tid & 15u;          // float4 index within row (0..15)
    unsigned h  = (tid >> 4) & 63u;
    unsigned c  = (tid >> 10) & 255u;
    unsigned b  = tid >> 18;          // 0..3 (low batch bits)

    unsigned g = c >> 6;              // group 0..3 (warp-uniform)
    unsigned lane = threadIdx.x & 31u;

    unsigned src_c, src_h;
    if (g == 0u)      { src_c = c + 64u; src_h = (h + 63u) & 63u; }
    else if (g == 1u) { src_c = c - 64u; src_h = (h + 1u)  & 63u; }
    else if (g == 2u) { src_c = c + 64u; src_h = h; }
    else              { src_c = c - 64u; src_h = h; }

    unsigned src = ((b * 256u + src_c) * 64u + src_h) * 16u + w4;

    // Front-batched independent streaming loads (MLP = 8)
    float4 v[ILP];
#pragma unroll
    for (int k = 0; k < ILP; k++)
        v[k] = __ldcs(&in[src + (unsigned)k * CHUNK]);

    if (g < 2u) {
#pragma unroll
        for (int k = 0; k < ILP; k++)
            __stcs(&out[tid + (unsigned)k * CHUNK], v[k]);
    } else if (g == 2u) {
        // out[w] = in[w-1]: {prev.w, v.x, v.y, v.z}; prev = lane-1 within the
        // 16-lane row group (wrap inside the half-warp row).
        unsigned srcLane = (lane & 16u) | ((lane + 15u) & 15u);
#pragma unroll
        for (int k = 0; k < ILP; k++) {
            float p = __shfl_sync(0xffffffffu, v[k].w, (int)srcLane);
            __stcs(&out[tid + (unsigned)k * CHUNK],
                   make_float4(p, v[k].x, v[k].y, v[k].z));
        }
    } else {
        // out[w] = in[w+1]: {v.y, v.z, v.w, next.x}; next = lane+1 within the
        // 16-lane row group (wrap).
        unsigned srcLane = (lane & 16u) | ((lane + 1u) & 15u);
#pragma unroll
        for (int k = 0; k < ILP; k++) {
            float n = __shfl_sync(0xffffffffu, v[k].x, (int)srcLane);
            __stcs(&out[tid + (unsigned)k * CHUNK],
                   make_float4(v[k].y, v[k].z, v[k].w, n));
        }
    }
}

extern "C" void kernel_launch(void* const* d_in, const int* in_sizes, int n_in,
                              void* d_out, int out_size)
{
    const float4* in  = (const float4*)d_in[0];
    float4*       out = (float4*)d_out;
    swap_roll_kernel<<<CHUNK / THREADS, THREADS>>>(in, out);
}

// round 4
// speedup vs baseline: 1.0228x; 1.0228x over previous
#include <cuda_runtime.h>

// Swap_18957985644706: channel-group roll permutation.
// x: (B=32, C=256, H=64, W=64) fp32, row-major.
// out group 0 (c in [0,64)):    x[b, c+64, (h-1)%64, w]
// out group 1 (c in [64,128)):  x[b, c-64, (h+1)%64, w]
// out group 2 (c in [128,192)): x[b, c+64, h, (w-1)%64]
// out group 3 (c in [192,256)): x[b, c-64, h, (w+1)%64]
//
// Converged design: ILP=4 (best measured MLP point), streaming cache hints
// (zero reuse, 268 MB total vs 126 MB L2), 512-thread blocks. Each thread
// handles 4 output float4s at tid + k*QUARTER; QUARTER = 2^21 lands in the
// batch bits so c/h/w4/group and shuffle lanes are shared across chunks.
// All memory ops are aligned 128-bit; the +/-1 W-shift is resolved with one
// warp shuffle across the 16-lane row group instead of misaligned loads.

static constexpr unsigned TOTAL_F4 = 32u * 256u * 64u * 16u;   // 8,388,608 = 2^23
static constexpr unsigned QUARTER  = TOTAL_F4 / 4u;            // 2,097,152 = 2^21
static constexpr unsigned THREADS  = 512u;

__global__ void __launch_bounds__(THREADS) swap_roll_kernel(
    const float4* __restrict__ in, float4* __restrict__ out)
{
    unsigned tid = blockIdx.x * THREADS + threadIdx.x;

    unsigned w4 = tid & 15u;          // float4 index within row (0..15)
    unsigned h  = (tid >> 4) & 63u;
    unsigned c  = (tid >> 10) & 255u;
    unsigned b  = tid >> 18;          // low batch bits

    unsigned g = c >> 6;              // group 0..3 (warp-uniform)
    unsigned lane = threadIdx.x & 31u;

    unsigned src_c, src_h;
    if (g == 0u)      { src_c = c + 64u; src_h = (h + 63u) & 63u; }
    else if (g == 1u) { src_c = c - 64u; src_h = (h + 1u)  & 63u; }
    else if (g == 2u) { src_c = c + 64u; src_h = h; }
    else              { src_c = c - 64u; src_h = h; }

    unsigned src = ((b * 256u + src_c) * 64u + src_h) * 16u + w4;

    // Front-batched independent streaming loads (MLP = 4)
    float4 v0 = __ldcs(&in[src]);
    float4 v1 = __ldcs(&in[src +      QUARTER]);
    float4 v2 = __ldcs(&in[src + 2u * QUARTER]);
    float4 v3 = __ldcs(&in[src + 3u * QUARTER]);

    if (g < 2u) {
        __stcs(&out[tid],                v0);
        __stcs(&out[tid +      QUARTER], v1);
        __stcs(&out[tid + 2u * QUARTER], v2);
        __stcs(&out[tid + 3u * QUARTER], v3);
    } else if (g == 2u) {
        // out[w] = in[w-1]: {prev.w, v.x, v.y, v.z}; prev = lane-1 within
        // the 16-lane row group (wrap inside the half-warp row).
        unsigned srcLane = (lane & 16u) | ((lane + 15u) & 15u);
        float p0 = __shfl_sync(0xffffffffu, v0.w, (int)srcLane);
        float p1 = __shfl_sync(0xffffffffu, v1.w, (int)srcLane);
        float p2 = __shfl_sync(0xffffffffu, v2.w, (int)srcLane);
        float p3 = __shfl_sync(0xffffffffu, v3.w, (int)srcLane);
        __stcs(&out[tid],                make_float4(p0, v0.x, v0.y, v0.z));
        __stcs(&out[tid +      QUARTER], make_float4(p1, v1.x, v1.y, v1.z));
        __stcs(&out[tid + 2u * QUARTER], make_float4(p2, v2.x, v2.y, v2.z));
        __stcs(&out[tid + 3u * QUARTER], make_float4(p3, v3.x, v3.y, v3.z));
    } else {
        // out[w] = in[w+1]: {v.y, v.z, v.w, next.x}; next = lane+1 within
        // the 16-lane row group (wrap).
        unsigned srcLane = (lane & 16u) | ((lane + 1u) & 15u);
        float n0 = __shfl_sync(0xffffffffu, v0.x, (int)srcLane);
        float n1 = __shfl_sync(0xffffffffu, v1.x, (int)srcLane);
        float n2 = __shfl_sync(0xffffffffu, v2.x, (int)srcLane);
        float n3 = __shfl_sync(0xffffffffu, v3.x, (int)srcLane);
        __stcs(&out[tid],                make_float4(v0.y, v0.z, v0.w, n0));
        __stcs(&out[tid +      QUARTER], make_float4(v1.y, v1.z, v1.w, n1));
        __stcs(&out[tid + 2u * QUARTER], make_float4(v2.y, v2.z, v2.w, n2));
        __stcs(&out[tid + 3u * QUARTER], make_float4(v3.y, v3.z, v3.w, n3));
    }
}

extern "C" void kernel_launch(void* const* d_in, const int* in_sizes, int n_in,
                              void* d_out, int out_size)
{
    const float4* in  = (const float4*)d_in[0];
    float4*       out = (float4*)d_out;
    swap_roll_kernel<<<QUARTER / THREADS, THREADS>>>(in, out);
}